// round 13
// baseline (speedup 1.0000x reference)
#include <cuda_runtime.h>
#include <cuda_fp16.h>
#include <cstdint>

// ---------------- constants ----------------
#define NROWS   8192
#define NHALF   4096
#define DIM     128
#define NT      64            // 128-row tiles
#define NTILES  2080          // upper triangle incl diag
#define SQRT_L2T 1.6986436f   // sqrt(2/ln2)

// dynamic smem: A tile @0 (32KB), B tile @32768 (32KB)
#define SM_A 0
#define SM_B 32768
#define SM_TOTAL 65536

// ---------------- device scratch ----------------
__device__ __half   g_repsh[NROWS * DIM];       // normalized * SQRT_L2T, fp16
__device__ float    g_posT[NHALF];              // exact fp32 positives / T
__device__ float    g_partial[NROWS * NT];      // [row][other-tile], one writer per slot
__device__ float    g_tilesum[NT];              // per-tile loss partial
__device__ unsigned g_done[NT];                 // per-tile write counters (zero-init; reset below)
__device__ unsigned g_fin;                      // finalized-tile counter (zero-init; reset below)

// ---------------- helpers ----------------
__device__ __forceinline__ uint32_t h2ex2(uint32_t x) {
    uint32_t y; asm("ex2.approx.f16x2 %0, %1;" : "=r"(y) : "r"(x)); return y;
}
__device__ __forceinline__ uint32_t hadd2(uint32_t a, uint32_t b) {
    uint32_t c; asm("add.f16x2 %0, %1, %2;" : "=r"(c) : "r"(a), "r"(b)); return c;
}
__device__ __forceinline__ uint32_t smem_u32(const void* p) {
    uint32_t a;
    asm("{ .reg .u64 t; cvta.to.shared.u64 t, %1; cvt.u32.u64 %0, t; }" : "=r"(a) : "l"(p));
    return a;
}
__device__ __forceinline__ void ldsm4(uint32_t* r, uint32_t addr) {
    asm volatile("ldmatrix.sync.aligned.m8n8.x4.shared.b16 {%0,%1,%2,%3}, [%4];"
        : "=r"(r[0]), "=r"(r[1]), "=r"(r[2]), "=r"(r[3]) : "r"(addr));
}
__device__ __forceinline__ void hmma16816(uint32_t* c, const uint32_t* a, uint32_t b0, uint32_t b1) {
    asm volatile(
        "mma.sync.aligned.m16n8k16.row.col.f16.f16.f16.f16 "
        "{%0,%1}, {%2,%3,%4,%5}, {%6,%7}, {%0,%1};\n"
        : "+r"(c[0]), "+r"(c[1])
        : "r"(a[0]), "r"(a[1]), "r"(a[2]), "r"(a[3]), "r"(b0), "r"(b1));
}
__device__ __forceinline__ uint32_t sw_off(int r, int c16) {
    return (uint32_t)r * 256 + (uint32_t)(c16 ^ (r & 7)) * 16;
}

// ---------------- kernel 1: normalize + positives (R11-proven: 2 warps/pair) ----------------
__global__ __launch_bounds__(256) void normpos_kernel(const float* __restrict__ p1,
                                                      const float* __restrict__ p2) {
    __shared__ float sm[4][2][3];
    int tid  = threadIdx.x;
    int warp = tid >> 5, lane = tid & 31;
    int pb = warp >> 1, hw = warp & 1;
    int i = blockIdx.x * 4 + pb;

    const float2* pa  = (const float2*)(p1 + (size_t)i * DIM) + hw * 32 + lane;
    const float2* pbb = (const float2*)(p2 + (size_t)i * DIM) + hw * 32 + lane;
    float2 av = *pa;
    float2 bv = *pbb;

    float sa  = av.x * av.x + av.y * av.y;
    float sb  = bv.x * bv.x + bv.y * bv.y;
    float sab = av.x * bv.x + av.y * bv.y;
#pragma unroll
    for (int o = 16; o > 0; o >>= 1) {
        sa  += __shfl_xor_sync(0xffffffffu, sa, o);
        sb  += __shfl_xor_sync(0xffffffffu, sb, o);
        sab += __shfl_xor_sync(0xffffffffu, sab, o);
    }
    if (lane == 0) {
        sm[pb][hw][0] = sa; sm[pb][hw][1] = sb; sm[pb][hw][2] = sab;
    }
    __syncthreads();
    sa  += sm[pb][hw ^ 1][0];
    sb  += sm[pb][hw ^ 1][1];
    sab += sm[pb][hw ^ 1][2];

    float na = fmaxf(sqrtf(sa), 1e-12f), nb = fmaxf(sqrtf(sb), 1e-12f);
    if (hw == 0 && lane == 0) g_posT[i] = 2.0f * sab / (na * nb);
    float ia = SQRT_L2T / na, ib = SQRT_L2T / nb;

    __half2 ha = __floats2half2_rn(av.x * ia, av.y * ia);
    __half2 hb = __floats2half2_rn(bv.x * ib, bv.y * ib);
    ((uint32_t*)(g_repsh + (size_t)i * DIM))[hw * 32 + lane]           = *(uint32_t*)&ha;
    ((uint32_t*)(g_repsh + (size_t)(i + NHALF) * DIM))[hw * 32 + lane] = *(uint32_t*)&hb;
}

// ---------------- in-sim tile finalize: 2 threads/row, fixed-order sums ----------------
// Returns (valid on tid 0 only): 1 if this was the 64th tile finalized.
__device__ __forceinline__ int fin_tile(int t, int tid, float* frow) {
    __threadfence();   // writers fenced before count; fence again before reading
    int half = tid & 1, r = tid >> 1;   // 256 threads -> 128 rows x 2 halves
    const float2* p = (const float2*)(g_partial + (size_t)(t * 128 + r) * NT) + half * 16;
    float s = 0.f;
#pragma unroll
    for (int q = 0; q < 16; q++) { float2 f = p[q]; s += f.x + f.y; }
    float other = __shfl_xor_sync(0xffffffffu, s, 1);
    if (half == 0) {
        float d = s + other;
        frow[r] = logf(d) - g_posT[(t * 128 + r) & (NHALF - 1)];
    }
    __syncthreads();
    for (int sft = 64; sft > 0; sft >>= 1) {
        if (tid < sft) frow[tid] += frow[tid + sft];
        __syncthreads();
    }
    int last = 0;
    if (tid == 0) {
        g_tilesum[t] = frow[0];
        __threadfence();
        last = (atomicAdd(&g_fin, 1u) + 1u == (unsigned)NT);
    }
    __syncthreads();
    return last;
}

// ---------------- kernel 2: HMMA tile + f16x2 exp + row/col sums + trailing finalize ----------------
__global__ __launch_bounds__(256, 3) void sim_kernel(float* __restrict__ out) {
    extern __shared__ char smc[];
    uint32_t smem = smem_u32(smc);
    __shared__ float rowpart[2][128];
    __shared__ float colpart[4][128];
    __shared__ float frow[128];
    __shared__ int s_doi, s_doj, s_last;

    int tid  = threadIdx.x;
    int warp = tid >> 5, lane = tid & 31;
    int wm = warp >> 1, wn = warp & 1;
    int gid = lane >> 2, t4 = lane & 3;

    // decode upper-triangle pair (ti <= tj)
    int b = blockIdx.x;
    int ti = (int)((129.0f - sqrtf(16641.0f - 8.0f * (float)b)) * 0.5f);
#define FROW_(t) ((t) * NT - (t) * ((t) - 1) / 2)
    while (FROW_(ti + 1) <= b) ti++;
    while (FROW_(ti) > b) ti--;
    int tj = ti + (b - FROW_(ti));
    int i0 = ti * 128, j0 = tj * 128;
    bool isdiag = (ti == tj);

    // load tiles: coalesced LDG.128, XOR-swizzled STS.128
    {
        const uint4* ga = (const uint4*)(g_repsh + (size_t)i0 * DIM);
#pragma unroll
        for (int it = 0; it < 8; it++) {
            int idx = tid + it * 256;
            int r = idx >> 4, c16 = idx & 15;
            *(uint4*)(smc + SM_A + sw_off(r, c16)) = ga[idx];
        }
        if (!isdiag) {
            const uint4* gb = (const uint4*)(g_repsh + (size_t)j0 * DIM);
#pragma unroll
            for (int it = 0; it < 8; it++) {
                int idx = tid + it * 256;
                int r = idx >> 4, c16 = idx & 15;
                *(uint4*)(smc + SM_B + sw_off(r, c16)) = gb[idx];
            }
        }
    }
    __syncthreads();
    uint32_t smB = smem + (isdiag ? SM_A : SM_B);

    // ldmatrix bases (validated layout)
    int rl = lane & 15, s = lane >> 4;
    uint32_t baseA[2], baseB[4];
    int kxA[2], kxB[4];
#pragma unroll
    for (int mf = 0; mf < 2; mf++) {
        int row = wm * 32 + mf * 16 + rl;
        int rx = row & 7;
        baseA[mf] = smem + SM_A + (uint32_t)row * 256 + (uint32_t)(s ^ (rx & 1)) * 16;
        kxA[mf] = rx >> 1;
    }
#pragma unroll
    for (int np = 0; np < 4; np++) {
        int row = wn * 64 + np * 16 + rl;
        int rx = row & 7;
        baseB[np] = smB + (uint32_t)row * 256 + (uint32_t)(s ^ (rx & 1)) * 16;
        kxB[np] = rx >> 1;
    }

    uint32_t acc[2][8][2];
#pragma unroll
    for (int mf = 0; mf < 2; mf++)
#pragma unroll
        for (int nf = 0; nf < 8; nf++) { acc[mf][nf][0] = 0u; acc[mf][nf][1] = 0u; }

#pragma unroll
    for (int k = 0; k < 8; k++) {
        uint32_t a[2][4], bf[4][4];
#pragma unroll
        for (int mf = 0; mf < 2; mf++)
            ldsm4(a[mf], baseA[mf] + (uint32_t)((k ^ kxA[mf]) << 5));
#pragma unroll
        for (int np = 0; np < 4; np++)
            ldsm4(bf[np], baseB[np] + (uint32_t)((k ^ kxB[np]) << 5));
#pragma unroll
        for (int nf = 0; nf < 8; nf++) {
            uint32_t b0 = bf[nf >> 1][nf & 1];
            uint32_t b1 = bf[nf >> 1][(nf & 1) + 2];
#pragma unroll
            for (int mf = 0; mf < 2; mf++)
                hmma16816(acc[mf][nf], a[mf], b0, b1);
        }
    }

    // epilogue: packed f16x2 ex2 + HADD2 partials
    float rs[2][2];
    uint32_t csh[8];
#pragma unroll
    for (int nf = 0; nf < 8; nf++) csh[nf] = 0u;

#pragma unroll
    for (int mf = 0; mf < 2; mf++)
#pragma unroll
        for (int h = 0; h < 2; h++) {
            int rowg = i0 + wm * 32 + mf * 16 + h * 8 + gid;
            uint32_t rsh = 0u;
#pragma unroll
            for (int nf = 0; nf < 8; nf++) {
                uint32_t e = h2ex2(acc[mf][nf][h]);
                if (isdiag) {
                    int colg = j0 + wn * 64 + nf * 8 + t4 * 2;
                    if (rowg == colg)     e &= 0xFFFF0000u;
                    if (rowg == colg + 1) e &= 0x0000FFFFu;
                }
                rsh = hadd2(rsh, e);
                csh[nf] = hadd2(csh[nf], e);
            }
            float2 fr = __half22float2(*(__half2*)&rsh);
            rs[mf][h] = fr.x + fr.y;
        }

#pragma unroll
    for (int mf = 0; mf < 2; mf++)
#pragma unroll
        for (int h = 0; h < 2; h++) {
            float v = rs[mf][h];
            v += __shfl_xor_sync(0xffffffffu, v, 1);
            v += __shfl_xor_sync(0xffffffffu, v, 2);
            if (t4 == 0)
                rowpart[wn][wm * 32 + mf * 16 + h * 8 + gid] = v;
        }

    if (!isdiag) {
#pragma unroll
        for (int nf = 0; nf < 8; nf++) {
            float2 fc = __half22float2(*(__half2*)&csh[nf]);
            float u0 = fc.x, u1 = fc.y;
#pragma unroll
            for (int o = 4; o <= 16; o <<= 1) {
                u0 += __shfl_xor_sync(0xffffffffu, u0, o);
                u1 += __shfl_xor_sync(0xffffffffu, u1, o);
            }
            if (gid == 0) {
                colpart[wm][wn * 64 + nf * 8 + t4 * 2]     = u0;
                colpart[wm][wn * 64 + nf * 8 + t4 * 2 + 1] = u1;
            }
        }
    }
    __syncthreads();

    if (tid < 128) {
        float rv = rowpart[0][tid] + rowpart[1][tid];
        g_partial[(size_t)(i0 + tid) * NT + tj] = rv;
        if (!isdiag) {
            float cv = colpart[0][tid] + colpart[1][tid] + colpart[2][tid] + colpart[3][tid];
            g_partial[(size_t)(j0 + tid) * NT + ti] = cv;
        }
    }

    // ---- completion counting (threadfence-reduction pattern; no spinning) ----
    __threadfence();
    __syncthreads();
    if (tid == 0) {
        s_last = 0;
        unsigned fi = atomicAdd(&g_done[ti], 1u) + 1u;
        s_doi = (fi == 64u);
        s_doj = 0;
        if (!isdiag) {
            unsigned fj = atomicAdd(&g_done[tj], 1u) + 1u;
            s_doj = (fj == 64u);
        }
    }
    __syncthreads();

    int lastflag = 0;
    if (s_doi) lastflag |= fin_tile(ti, tid, frow);
    if (s_doj) lastflag |= fin_tile(tj, tid, frow);
    if (tid == 0 && lastflag) s_last = 1;
    __syncthreads();

    if (s_last) {
        __threadfence();
        if (tid < NT) frow[tid] = g_tilesum[tid];
        __syncthreads();
        if (tid == 0) {
            float tot = 0.f;
#pragma unroll
            for (int t2 = 0; t2 < NT; t2++) tot += frow[t2];
            out[0] = tot / (float)NROWS;
            // reset state for next graph replay
            g_fin = 0u;
#pragma unroll
            for (int t2 = 0; t2 < NT; t2++) g_done[t2] = 0u;
        }
    }
}

// ---------------- launch ----------------
extern "C" void kernel_launch(void* const* d_in, const int* in_sizes, int n_in,
                              void* d_out, int out_size) {
    const float* p1 = (const float*)d_in[0];
    const float* p2 = (const float*)d_in[1];
    float* out = (float*)d_out;

    cudaFuncSetAttribute(sim_kernel, cudaFuncAttributeMaxDynamicSharedMemorySize, SM_TOTAL);

    normpos_kernel<<<NHALF / 4, 256>>>(p1, p2);
    sim_kernel<<<NTILES, 256, SM_TOTAL>>>(out);
}

// round 14
// speedup vs baseline: 1.4421x; 1.4421x over previous
#include <cuda_runtime.h>
#include <cuda_fp16.h>
#include <cstdint>

// ---------------- constants ----------------
#define NROWS   8192
#define NHALF   4096
#define DIM     128
#define NT      64            // 128-row tiles
#define NTILES  2080          // upper triangle incl diag
#define SQRT_L2T 1.6986436f   // sqrt(2/ln2); (s*a)·(s*b) = (2/ln2)*sim -> ex2 direct

// dynamic smem: A tile @0 (32KB), B tile @32768 (32KB)
#define SM_A 0
#define SM_B 32768
#define SM_TOTAL 65536

// ---------------- device scratch ----------------
__device__ __half   g_repsh[NROWS * DIM];       // normalized * SQRT_L2T, fp16
__device__ float    g_posT[NHALF];              // exact fp32 positives / T
__device__ float    g_partial[NROWS * NT];      // [row][other-tile], one writer per slot
__device__ float    g_blocksum[1024];
__device__ unsigned g_ticket;                   // zero-init; reset by last block each run

// ---------------- helpers ----------------
__device__ __forceinline__ uint32_t h2ex2(uint32_t x) {
    uint32_t y; asm("ex2.approx.f16x2 %0, %1;" : "=r"(y) : "r"(x)); return y;
}
__device__ __forceinline__ uint32_t hadd2(uint32_t a, uint32_t b) {
    uint32_t c; asm("add.f16x2 %0, %1, %2;" : "=r"(c) : "r"(a), "r"(b)); return c;
}
__device__ __forceinline__ uint32_t smem_u32(const void* p) {
    uint32_t a;
    asm("{ .reg .u64 t; cvta.to.shared.u64 t, %1; cvt.u32.u64 %0, t; }" : "=r"(a) : "l"(p));
    return a;
}
__device__ __forceinline__ void ldsm4(uint32_t* r, uint32_t addr) {
    asm volatile("ldmatrix.sync.aligned.m8n8.x4.shared.b16 {%0,%1,%2,%3}, [%4];"
        : "=r"(r[0]), "=r"(r[1]), "=r"(r[2]), "=r"(r[3]) : "r"(addr));
}
// f16 x f16 -> f16 accumulate
__device__ __forceinline__ void hmma16816(uint32_t* c, const uint32_t* a, uint32_t b0, uint32_t b1) {
    asm volatile(
        "mma.sync.aligned.m16n8k16.row.col.f16.f16.f16.f16 "
        "{%0,%1}, {%2,%3,%4,%5}, {%6,%7}, {%0,%1};\n"
        : "+r"(c[0]), "+r"(c[1])
        : "r"(a[0]), "r"(a[1]), "r"(a[2]), "r"(a[3]), "r"(b0), "r"(b1));
}
// swizzled byte offset of (row, 16B-chunk) in a 128x256B tile: chunk ^ (row&7)
__device__ __forceinline__ uint32_t sw_off(int r, int c16) {
    return (uint32_t)r * 256 + (uint32_t)(c16 ^ (r & 7)) * 16;
}

// ---------------- kernel 1: normalize + positives; 2 warps per pair (8192 warps) ----------------
__global__ __launch_bounds__(256) void normpos_kernel(const float* __restrict__ p1,
                                                      const float* __restrict__ p2) {
    __shared__ float sm[4][2][3];
    int tid  = threadIdx.x;
    int warp = tid >> 5, lane = tid & 31;
    int pb = warp >> 1, hw = warp & 1;
    int i = blockIdx.x * 4 + pb;                      // pair 0..4095

    const float2* pa  = (const float2*)(p1 + (size_t)i * DIM) + hw * 32 + lane;
    const float2* pbb = (const float2*)(p2 + (size_t)i * DIM) + hw * 32 + lane;
    float2 av = *pa;
    float2 bv = *pbb;

    float sa  = av.x * av.x + av.y * av.y;
    float sb  = bv.x * bv.x + bv.y * bv.y;
    float sab = av.x * bv.x + av.y * bv.y;
#pragma unroll
    for (int o = 16; o > 0; o >>= 1) {
        sa  += __shfl_xor_sync(0xffffffffu, sa, o);
        sb  += __shfl_xor_sync(0xffffffffu, sb, o);
        sab += __shfl_xor_sync(0xffffffffu, sab, o);
    }
    if (lane == 0) {
        sm[pb][hw][0] = sa; sm[pb][hw][1] = sb; sm[pb][hw][2] = sab;
    }
    __syncthreads();
    sa  += sm[pb][hw ^ 1][0];
    sb  += sm[pb][hw ^ 1][1];
    sab += sm[pb][hw ^ 1][2];

    float na = fmaxf(sqrtf(sa), 1e-12f), nb = fmaxf(sqrtf(sb), 1e-12f);
    if (hw == 0 && lane == 0) g_posT[i] = 2.0f * sab / (na * nb);
    float ia = SQRT_L2T / na, ib = SQRT_L2T / nb;

    __half2 ha = __floats2half2_rn(av.x * ia, av.y * ia);
    __half2 hb = __floats2half2_rn(bv.x * ib, bv.y * ib);
    ((uint32_t*)(g_repsh + (size_t)i * DIM))[hw * 32 + lane]           = *(uint32_t*)&ha;
    ((uint32_t*)(g_repsh + (size_t)(i + NHALF) * DIM))[hw * 32 + lane] = *(uint32_t*)&hb;
}

// ---------------- kernel 2: HMMA tile + f16x2 exp + row/col sums (proven) ----------------
__global__ __launch_bounds__(256, 3) void sim_kernel() {
    extern __shared__ char smc[];
    uint32_t smem = smem_u32(smc);
    __shared__ float rowpart[2][128];
    __shared__ float colpart[4][128];

    int tid  = threadIdx.x;
    int warp = tid >> 5, lane = tid & 31;
    int wm = warp >> 1, wn = warp & 1;
    int gid = lane >> 2, t4 = lane & 3;

    // decode upper-triangle pair (ti <= tj)
    int b = blockIdx.x;
    int ti = (int)((129.0f - sqrtf(16641.0f - 8.0f * (float)b)) * 0.5f);
#define FROW(t) ((t) * NT - (t) * ((t) - 1) / 2)
    while (FROW(ti + 1) <= b) ti++;
    while (FROW(ti) > b) ti--;
    int tj = ti + (b - FROW(ti));
    int i0 = ti * 128, j0 = tj * 128;
    bool isdiag = (ti == tj);

    // load tiles: coalesced LDG.128, XOR-swizzled STS.128
    {
        const uint4* ga = (const uint4*)(g_repsh + (size_t)i0 * DIM);
#pragma unroll
        for (int it = 0; it < 8; it++) {
            int idx = tid + it * 256;               // 0..2047
            int r = idx >> 4, c16 = idx & 15;
            *(uint4*)(smc + SM_A + sw_off(r, c16)) = ga[idx];
        }
        if (!isdiag) {
            const uint4* gb = (const uint4*)(g_repsh + (size_t)j0 * DIM);
#pragma unroll
            for (int it = 0; it < 8; it++) {
                int idx = tid + it * 256;
                int r = idx >> 4, c16 = idx & 15;
                *(uint4*)(smc + SM_B + sw_off(r, c16)) = gb[idx];
            }
        }
    }
    __syncthreads();
    uint32_t smB = smem + (isdiag ? SM_A : SM_B);

    // ldmatrix bases (validated layout)
    int rl = lane & 15, s = lane >> 4;
    uint32_t baseA[2], baseB[4];
    int kxA[2], kxB[4];
#pragma unroll
    for (int mf = 0; mf < 2; mf++) {
        int row = wm * 32 + mf * 16 + rl;
        int rx = row & 7;
        baseA[mf] = smem + SM_A + (uint32_t)row * 256 + (uint32_t)(s ^ (rx & 1)) * 16;
        kxA[mf] = rx >> 1;
    }
#pragma unroll
    for (int np = 0; np < 4; np++) {
        int row = wn * 64 + np * 16 + rl;
        int rx = row & 7;
        baseB[np] = smB + (uint32_t)row * 256 + (uint32_t)(s ^ (rx & 1)) * 16;
        kxB[np] = rx >> 1;
    }

    uint32_t acc[2][8][2];   // f16x2 accumulators
#pragma unroll
    for (int mf = 0; mf < 2; mf++)
#pragma unroll
        for (int nf = 0; nf < 8; nf++) { acc[mf][nf][0] = 0u; acc[mf][nf][1] = 0u; }

#pragma unroll
    for (int k = 0; k < 8; k++) {
        uint32_t a[2][4], bf[4][4];
#pragma unroll
        for (int mf = 0; mf < 2; mf++)
            ldsm4(a[mf], baseA[mf] + (uint32_t)((k ^ kxA[mf]) << 5));
#pragma unroll
        for (int np = 0; np < 4; np++)
            ldsm4(bf[np], baseB[np] + (uint32_t)((k ^ kxB[np]) << 5));
#pragma unroll
        for (int nf = 0; nf < 8; nf++) {
            uint32_t b0 = bf[nf >> 1][nf & 1];
            uint32_t b1 = bf[nf >> 1][(nf & 1) + 2];
#pragma unroll
            for (int mf = 0; mf < 2; mf++)
                hmma16816(acc[mf][nf], a[mf], b0, b1);
        }
    }

    // epilogue: packed f16x2 ex2 + HADD2 partials (bounded <=60, f16-safe)
    float rs[2][2];
    uint32_t csh[8];
#pragma unroll
    for (int nf = 0; nf < 8; nf++) csh[nf] = 0u;

#pragma unroll
    for (int mf = 0; mf < 2; mf++)
#pragma unroll
        for (int h = 0; h < 2; h++) {
            int rowg = i0 + wm * 32 + mf * 16 + h * 8 + gid;
            uint32_t rsh = 0u;
#pragma unroll
            for (int nf = 0; nf < 8; nf++) {
                uint32_t e = h2ex2(acc[mf][nf][h]);
                if (isdiag) {
                    int colg = j0 + wn * 64 + nf * 8 + t4 * 2;
                    if (rowg == colg)     e &= 0xFFFF0000u;   // zero lo half
                    if (rowg == colg + 1) e &= 0x0000FFFFu;   // zero hi half
                }
                rsh = hadd2(rsh, e);
                csh[nf] = hadd2(csh[nf], e);
            }
            float2 fr = __half22float2(*(__half2*)&rsh);
            rs[mf][h] = fr.x + fr.y;
        }

    // row sums: quad-reduce, per-wn halves into smem
#pragma unroll
    for (int mf = 0; mf < 2; mf++)
#pragma unroll
        for (int h = 0; h < 2; h++) {
            float v = rs[mf][h];
            v += __shfl_xor_sync(0xffffffffu, v, 1);
            v += __shfl_xor_sync(0xffffffffu, v, 2);
            if (t4 == 0)
                rowpart[wn][wm * 32 + mf * 16 + h * 8 + gid] = v;
        }

    // col sums (off-diag only): reduce across gid lanes
    if (!isdiag) {
#pragma unroll
        for (int nf = 0; nf < 8; nf++) {
            float2 fc = __half22float2(*(__half2*)&csh[nf]);
            float u0 = fc.x, u1 = fc.y;
#pragma unroll
            for (int o = 4; o <= 16; o <<= 1) {
                u0 += __shfl_xor_sync(0xffffffffu, u0, o);
                u1 += __shfl_xor_sync(0xffffffffu, u1, o);
            }
            if (gid == 0) {
                colpart[wm][wn * 64 + nf * 8 + t4 * 2]     = u0;
                colpart[wm][wn * 64 + nf * 8 + t4 * 2 + 1] = u1;
            }
        }
    }
    __syncthreads();

    if (tid < 128) {
        float rv = rowpart[0][tid] + rowpart[1][tid];
        g_partial[(size_t)(i0 + tid) * NT + tj] = rv;
        if (!isdiag) {
            float cv = colpart[0][tid] + colpart[1][tid] + colpart[2][tid] + colpart[3][tid];
            g_partial[(size_t)(j0 + tid) * NT + ti] = cv;
        }
    }
}

// ---------------- kernel 3: fused finalize (last-block pattern) ----------------
__global__ void finalize_kernel(float* __restrict__ out) {
    __shared__ float part[8];
    __shared__ float red[256];
    __shared__ int lastflag;
    int tid = threadIdx.x;
    int w = tid >> 5, lane = tid & 31;
    int r = blockIdx.x * 8 + w;
    float2 v = ((const float2*)(g_partial + (size_t)r * NT))[lane];
    float d = v.x + v.y;
#pragma unroll
    for (int o = 16; o > 0; o >>= 1) d += __shfl_xor_sync(0xffffffffu, d, o);
    if (lane == 0) part[w] = logf(d) - g_posT[r & (NHALF - 1)];
    __syncthreads();
    if (tid == 0) {
        float ssum = 0.f;
#pragma unroll
        for (int k = 0; k < 8; k++) ssum += part[k];
        g_blocksum[blockIdx.x] = ssum;
        __threadfence();
        unsigned t = atomicAdd(&g_ticket, 1u);
        lastflag = (t == 1023u);
    }
    __syncthreads();
    if (lastflag) {
        float a = g_blocksum[tid] + g_blocksum[tid + 256]
                + g_blocksum[tid + 512] + g_blocksum[tid + 768];
        red[tid] = a;
        __syncthreads();
        for (int sft = 128; sft > 0; sft >>= 1) {
            if (tid < sft) red[tid] += red[tid + sft];
            __syncthreads();
        }
        if (tid == 0) {
            out[0] = red[0] / (float)NROWS;
            g_ticket = 0u;    // reset for next graph replay
        }
    }
}

// ---------------- launch ----------------
extern "C" void kernel_launch(void* const* d_in, const int* in_sizes, int n_in,
                              void* d_out, int out_size) {
    const float* p1 = (const float*)d_in[0];
    const float* p2 = (const float*)d_in[1];
    float* out = (float*)d_out;

    cudaFuncSetAttribute(sim_kernel, cudaFuncAttributeMaxDynamicSharedMemorySize, SM_TOTAL);

    normpos_kernel<<<NHALF / 4, 256>>>(p1, p2);
    sim_kernel<<<NTILES, 256, SM_TOTAL>>>();
    finalize_kernel<<<NROWS / 8, 256>>>(out);
}

// round 15
// speedup vs baseline: 1.5852x; 1.0992x over previous
#include <cuda_runtime.h>
#include <cuda_fp16.h>
#include <cstdint>

// ---------------- constants ----------------
#define NROWS   8192
#define NHALF   4096
#define DIM     128
#define NT      64            // 128-row tiles
#define NTILES  2080          // upper triangle incl diag
#define SQRT_L2T 1.6986436f   // sqrt(2/ln2); (s*a)·(s*b) = (2/ln2)*sim -> ex2 direct

// dynamic smem: A tile @0 (16KB), B tile @16384 (16KB) — e4m3 rows are 128B
#define SM_A 0
#define SM_B 16384
#define SM_TOTAL 32768

// ---------------- device scratch ----------------
__device__ uint8_t  g_repsq[NROWS * DIM];       // normalized * SQRT_L2T, e4m3
__device__ float    g_posT[NHALF];              // exact fp32 positives / T
__device__ float    g_partial[NROWS * NT];      // [row][other-tile], one writer per slot
__device__ float    g_blocksum[1024];
__device__ unsigned g_ticket;                   // zero-init; reset by last block each run

// ---------------- helpers ----------------
__device__ __forceinline__ uint32_t h2ex2(uint32_t x) {
    uint32_t y; asm("ex2.approx.f16x2 %0, %1;" : "=r"(y) : "r"(x)); return y;
}
__device__ __forceinline__ uint32_t hadd2(uint32_t a, uint32_t b) {
    uint32_t c; asm("add.f16x2 %0, %1, %2;" : "=r"(c) : "r"(a), "r"(b)); return c;
}
__device__ __forceinline__ uint32_t smem_u32(const void* p) {
    uint32_t a;
    asm("{ .reg .u64 t; cvta.to.shared.u64 t, %1; cvt.u32.u64 %0, t; }" : "=r"(a) : "l"(p));
    return a;
}
__device__ __forceinline__ void ldsm4(uint32_t* r, uint32_t addr) {
    asm volatile("ldmatrix.sync.aligned.m8n8.x4.shared.b16 {%0,%1,%2,%3}, [%4];"
        : "=r"(r[0]), "=r"(r[1]), "=r"(r[2]), "=r"(r[3]) : "r"(addr));
}
// e4m3 x e4m3 -> f16 accumulate, K=32
__device__ __forceinline__ void qmma16832(uint32_t* c, const uint32_t* a, uint32_t b0, uint32_t b1) {
    asm volatile(
        "mma.sync.aligned.m16n8k32.row.col.f16.e4m3.e4m3.f16 "
        "{%0,%1}, {%2,%3,%4,%5}, {%6,%7}, {%0,%1};\n"
        : "+r"(c[0]), "+r"(c[1])
        : "r"(a[0]), "r"(a[1]), "r"(a[2]), "r"(a[3]), "r"(b0), "r"(b1));
}
// pack two floats -> e4m3x2 (a=upper, b=lower per PTX operand order)
__device__ __forceinline__ uint16_t f2e4m3x2(float lo, float hi) {
    uint16_t d;
    asm("cvt.rn.satfinite.e4m3x2.f32 %0, %1, %2;" : "=h"(d) : "f"(hi), "f"(lo));
    return d;
}

// ---------------- kernel 1: normalize + positives + e4m3 quantize (2 warps/pair) ----------------
__global__ __launch_bounds__(256) void normpos_kernel(const float* __restrict__ p1,
                                                      const float* __restrict__ p2) {
    __shared__ float sm[4][2][3];
    int tid  = threadIdx.x;
    int warp = tid >> 5, lane = tid & 31;
    int pb = warp >> 1, hw = warp & 1;
    int i = blockIdx.x * 4 + pb;                      // pair 0..4095

    const float2* pa  = (const float2*)(p1 + (size_t)i * DIM) + hw * 32 + lane;
    const float2* pbb = (const float2*)(p2 + (size_t)i * DIM) + hw * 32 + lane;
    float2 av = *pa;
    float2 bv = *pbb;

    float sa  = av.x * av.x + av.y * av.y;
    float sb  = bv.x * bv.x + bv.y * bv.y;
    float sab = av.x * bv.x + av.y * bv.y;
#pragma unroll
    for (int o = 16; o > 0; o >>= 1) {
        sa  += __shfl_xor_sync(0xffffffffu, sa, o);
        sb  += __shfl_xor_sync(0xffffffffu, sb, o);
        sab += __shfl_xor_sync(0xffffffffu, sab, o);
    }
    if (lane == 0) {
        sm[pb][hw][0] = sa; sm[pb][hw][1] = sb; sm[pb][hw][2] = sab;
    }
    __syncthreads();
    sa  += sm[pb][hw ^ 1][0];
    sb  += sm[pb][hw ^ 1][1];
    sab += sm[pb][hw ^ 1][2];

    float na = fmaxf(sqrtf(sa), 1e-12f), nb = fmaxf(sqrtf(sb), 1e-12f);
    if (hw == 0 && lane == 0) g_posT[i] = 2.0f * sab / (na * nb);
    float ia = SQRT_L2T / na, ib = SQRT_L2T / nb;

    uint16_t qa = f2e4m3x2(av.x * ia, av.y * ia);
    uint16_t qb = f2e4m3x2(bv.x * ib, bv.y * ib);
    ((uint16_t*)(g_repsq + (size_t)i * DIM))[hw * 32 + lane]           = qa;
    ((uint16_t*)(g_repsq + (size_t)(i + NHALF) * DIM))[hw * 32 + lane] = qb;
}

// ---------------- kernel 2: FP8 MMA tile + f16x2 exp + row/col sums ----------------
// 2080 CTAs (one upper-triangle 128x128 tile), 256 threads (8 warps, 4 wm x 2 wn).
__global__ __launch_bounds__(256, 3) void sim_kernel() {
    extern __shared__ char smc[];
    uint32_t smem = smem_u32(smc);
    __shared__ float rowpart[2][128];
    __shared__ float colpart[4][128];

    int tid  = threadIdx.x;
    int warp = tid >> 5, lane = tid & 31;
    int wm = warp >> 1, wn = warp & 1;
    int gid = lane >> 2, t4 = lane & 3;

    // decode upper-triangle pair (ti <= tj)
    int b = blockIdx.x;
    int ti = (int)((129.0f - sqrtf(16641.0f - 8.0f * (float)b)) * 0.5f);
#define FROW(t) ((t) * NT - (t) * ((t) - 1) / 2)
    while (FROW(ti + 1) <= b) ti++;
    while (FROW(ti) > b) ti--;
    int tj = ti + (b - FROW(ti));
    int i0 = ti * 128, j0 = tj * 128;
    bool isdiag = (ti == tj);

    // load tiles: coalesced LDG.128, XOR-swizzled STS.128 (128B rows, 8x16B chunks)
    {
        const uint4* ga = (const uint4*)(g_repsq + (size_t)i0 * DIM);
#pragma unroll
        for (int it = 0; it < 4; it++) {
            int idx = tid + it * 256;               // 0..1023
            int r = idx >> 3, c16 = idx & 7;
            *(uint4*)(smc + SM_A + r * 128 + ((c16 ^ (r & 7)) << 4)) = ga[idx];
        }
        if (!isdiag) {
            const uint4* gb = (const uint4*)(g_repsq + (size_t)j0 * DIM);
#pragma unroll
            for (int it = 0; it < 4; it++) {
                int idx = tid + it * 256;
                int r = idx >> 3, c16 = idx & 7;
                *(uint4*)(smc + SM_B + r * 128 + ((c16 ^ (r & 7)) << 4)) = gb[idx];
            }
        }
    }
    __syncthreads();
    uint32_t smB = smem + (isdiag ? SM_A : SM_B);

    // A ldmatrix bases (R5-verified byte-tile layout)
    int rl = lane & 15, sA = lane >> 4;
    uint32_t baseA[2]; int kxA[2];
#pragma unroll
    for (int mf = 0; mf < 2; mf++) {
        int row = wm * 32 + mf * 16 + rl;
        int rx = row & 7;
        baseA[mf] = smem + SM_A + (uint32_t)row * 128 + (uint32_t)((sA ^ (rx & 1)) << 4);
        kxA[mf] = rx >> 1;
    }
    // B ldmatrix bases (R5-verified)
    int coll = (lane & 7) | ((lane >> 4) << 3);
    int sB = (lane >> 3) & 1;
    uint32_t baseB[4]; int kxB[4];
#pragma unroll
    for (int np = 0; np < 4; np++) {
        int col = wn * 64 + np * 16 + coll;
        int cx = col & 7;
        baseB[np] = smB + (uint32_t)col * 128 + (uint32_t)((sB ^ (cx & 1)) << 4);
        kxB[np] = cx >> 1;
    }

    uint32_t acc[2][8][2];   // f16x2 accumulators
#pragma unroll
    for (int mf = 0; mf < 2; mf++)
#pragma unroll
        for (int nf = 0; nf < 8; nf++) { acc[mf][nf][0] = 0u; acc[mf][nf][1] = 0u; }

#pragma unroll
    for (int k = 0; k < 4; k++) {     // 4 k32 steps over K=128
        uint32_t a[2][4], bq[4][4];
#pragma unroll
        for (int mf = 0; mf < 2; mf++)
            ldsm4(a[mf], baseA[mf] + (uint32_t)((k ^ kxA[mf]) << 5));
#pragma unroll
        for (int np = 0; np < 4; np++)
            ldsm4(bq[np], baseB[np] + (uint32_t)((k ^ kxB[np]) << 5));
#pragma unroll
        for (int nf = 0; nf < 8; nf++) {
            uint32_t b0 = bq[nf >> 1][(nf & 1) * 2];
            uint32_t b1 = bq[nf >> 1][(nf & 1) * 2 + 1];
#pragma unroll
            for (int mf = 0; mf < 2; mf++)
                qmma16832(acc[mf][nf], a[mf], b0, b1);
        }
    }

    // epilogue: packed f16x2 ex2 + HADD2 partials (bounded <=60, f16-safe)
    float rs[2][2];
    uint32_t csh[8];
#pragma unroll
    for (int nf = 0; nf < 8; nf++) csh[nf] = 0u;

#pragma unroll
    for (int mf = 0; mf < 2; mf++)
#pragma unroll
        for (int h = 0; h < 2; h++) {
            int rowg = i0 + wm * 32 + mf * 16 + h * 8 + gid;
            uint32_t rsh = 0u;
#pragma unroll
            for (int nf = 0; nf < 8; nf++) {
                uint32_t e = h2ex2(acc[mf][nf][h]);
                if (isdiag) {
                    int colg = j0 + wn * 64 + nf * 8 + t4 * 2;
                    if (rowg == colg)     e &= 0xFFFF0000u;   // zero lo half
                    if (rowg == colg + 1) e &= 0x0000FFFFu;   // zero hi half
                }
                rsh = hadd2(rsh, e);
                csh[nf] = hadd2(csh[nf], e);
            }
            float2 fr = __half22float2(*(__half2*)&rsh);
            rs[mf][h] = fr.x + fr.y;
        }

    // row sums: quad-reduce, per-wn halves into smem
#pragma unroll
    for (int mf = 0; mf < 2; mf++)
#pragma unroll
        for (int h = 0; h < 2; h++) {
            float v = rs[mf][h];
            v += __shfl_xor_sync(0xffffffffu, v, 1);
            v += __shfl_xor_sync(0xffffffffu, v, 2);
            if (t4 == 0)
                rowpart[wn][wm * 32 + mf * 16 + h * 8 + gid] = v;
        }

    // col sums (off-diag only): reduce across gid lanes
    if (!isdiag) {
#pragma unroll
        for (int nf = 0; nf < 8; nf++) {
            float2 fc = __half22float2(*(__half2*)&csh[nf]);
            float u0 = fc.x, u1 = fc.y;
#pragma unroll
            for (int o = 4; o <= 16; o <<= 1) {
                u0 += __shfl_xor_sync(0xffffffffu, u0, o);
                u1 += __shfl_xor_sync(0xffffffffu, u1, o);
            }
            if (gid == 0) {
                colpart[wm][wn * 64 + nf * 8 + t4 * 2]     = u0;
                colpart[wm][wn * 64 + nf * 8 + t4 * 2 + 1] = u1;
            }
        }
    }
    __syncthreads();

    if (tid < 128) {
        float rv = rowpart[0][tid] + rowpart[1][tid];
        g_partial[(size_t)(i0 + tid) * NT + tj] = rv;
        if (!isdiag) {
            float cv = colpart[0][tid] + colpart[1][tid] + colpart[2][tid] + colpart[3][tid];
            g_partial[(size_t)(j0 + tid) * NT + ti] = cv;
        }
    }
}

// ---------------- kernel 3: fused finalize (last-block pattern) ----------------
__global__ void finalize_kernel(float* __restrict__ out) {
    __shared__ float part[8];
    __shared__ float red[256];
    __shared__ int lastflag;
    int tid = threadIdx.x;
    int w = tid >> 5, lane = tid & 31;
    int r = blockIdx.x * 8 + w;
    float2 v = ((const float2*)(g_partial + (size_t)r * NT))[lane];
    float d = v.x + v.y;
#pragma unroll
    for (int o = 16; o > 0; o >>= 1) d += __shfl_xor_sync(0xffffffffu, d, o);
    if (lane == 0) part[w] = logf(d) - g_posT[r & (NHALF - 1)];
    __syncthreads();
    if (tid == 0) {
        float ssum = 0.f;
#pragma unroll
        for (int k = 0; k < 8; k++) ssum += part[k];
        g_blocksum[blockIdx.x] = ssum;
        __threadfence();
        unsigned t = atomicAdd(&g_ticket, 1u);
        lastflag = (t == 1023u);
    }
    __syncthreads();
    if (lastflag) {
        float a = g_blocksum[tid] + g_blocksum[tid + 256]
                + g_blocksum[tid + 512] + g_blocksum[tid + 768];
        red[tid] = a;
        __syncthreads();
        for (int sft = 128; sft > 0; sft >>= 1) {
            if (tid < sft) red[tid] += red[tid + sft];
            __syncthreads();
        }
        if (tid == 0) {
            out[0] = red[0] / (float)NROWS;
            g_ticket = 0u;    // reset for next graph replay
        }
    }
}

// ---------------- launch ----------------
extern "C" void kernel_launch(void* const* d_in, const int* in_sizes, int n_in,
                              void* d_out, int out_size) {
    const float* p1 = (const float*)d_in[0];
    const float* p2 = (const float*)d_in[1];
    float* out = (float*)d_out;

    cudaFuncSetAttribute(sim_kernel, cudaFuncAttributeMaxDynamicSharedMemorySize, SM_TOTAL);

    normpos_kernel<<<NHALF / 4, 256>>>(p1, p2);
    sim_kernel<<<NTILES, 256, SM_TOTAL>>>();
    finalize_kernel<<<NROWS / 8, 256>>>(out);
}